// round 3
// baseline (speedup 1.0000x reference)
#include <cuda_runtime.h>
#include <cstddef>

#define N_NODES 100000
#define N_EDGES 3200000
#define D_IN    128
#define D_HID   128
#define D_OUT   64

// ---------------- scratch (no allocation allowed) ----------------
__device__ __align__(16) float g_cnt [N_NODES];
__device__ __align__(16) float g_inv [N_NODES];
__device__ __align__(16) float g_agg1[(size_t)N_NODES * D_IN];   // scatter-sum of x[src]*w
__device__ __align__(16) float g_t   [(size_t)N_NODES * D_OUT];  // h @ W_l2^T
__device__ __align__(16) float g_agg2[(size_t)N_NODES * D_OUT];  // scatter-sum of t[src]*w
__device__ __align__(16) float g_h   [(size_t)N_NODES * D_HID];  // fallback h storage
__device__ int g_idx64;   // 1 if edge_index is int64, 0 if int32

// vectorized fp32 reduction (sm_90+): one RED per 16 bytes
__device__ __forceinline__ void red_add_v4(float* p, float4 v) {
    asm volatile(
        "{\n\t.reg .u64 pg;\n\t"
        "cvta.to.global.u64 pg, %0;\n\t"
        "red.global.add.v4.f32 [pg], {%1,%2,%3,%4};\n\t}"
        :: "l"(p), "f"(v.x), "f"(v.y), "f"(v.z), "f"(v.w)
        : "memory");
}

// Load edge endpoint #e (src if half==0, dst if half==1) honoring detected dtype.
__device__ __forceinline__ int load_idx(const void* ei, int e, int half, int mode64) {
    if (mode64) {
        long long v = __ldg(reinterpret_cast<const long long*>(ei) +
                            (size_t)half * N_EDGES + e);
        return (int)v;
    } else {
        return __ldg(reinterpret_cast<const int*>(ei) + (size_t)half * N_EDGES + e);
    }
}

// ---------------- dtype detection ----------------
// int64 little-endian values < 2^31 -> every odd 32-bit word is zero.
// int32 node indices over 8192 words cannot be all-zero at odd positions.
__global__ void detect_kernel(const int* __restrict__ ei_words) {
    __shared__ int any_nonzero;
    if (threadIdx.x == 0) any_nonzero = 0;
    __syncthreads();
    int acc = 0;
    for (int i = threadIdx.x; i < 4096; i += blockDim.x)
        acc |= ei_words[2 * i + 1];
    if (acc) atomicOr(&any_nonzero, 1);
    __syncthreads();
    if (threadIdx.x == 0) g_idx64 = any_nonzero ? 0 : 1;
}

// ---------------- init: zero accumulators ----------------
__global__ void init_kernel() {
    size_t i = (size_t)blockIdx.x * blockDim.x + threadIdx.x;
    size_t stride = (size_t)gridDim.x * blockDim.x;
    for (size_t k = i; k < N_NODES; k += stride) g_cnt[k] = 0.f;
    float4 z = make_float4(0.f, 0.f, 0.f, 0.f);
    for (size_t k = i; k < (size_t)N_NODES * D_IN / 4; k += stride)
        reinterpret_cast<float4*>(g_agg1)[k] = z;
    for (size_t k = i; k < (size_t)N_NODES * D_OUT / 4; k += stride)
        reinterpret_cast<float4*>(g_agg2)[k] = z;
}

// ---------------- layer-1 scatter: agg1[dst] += x[src]*w ; cnt[dst] += 1 ----------------
// one warp per edge, each lane handles 4 consecutive features (float4)
__global__ void scatter1_kernel(const float* __restrict__ x,
                                const void* __restrict__ ei,
                                const float* __restrict__ ew) {
    int warp = (blockIdx.x * blockDim.x + threadIdx.x) >> 5;
    if (warp >= N_EDGES) return;
    int lane = threadIdx.x & 31;
    int mode64 = g_idx64;
    int s = load_idx(ei, warp, 0, mode64);
    int d = load_idx(ei, warp, 1, mode64);
    if ((unsigned)s >= N_NODES || (unsigned)d >= N_NODES) return;  // guard
    float w = __ldg(&ew[warp]);
    float4 v = __ldg(reinterpret_cast<const float4*>(x + (size_t)s * D_IN) + lane);
    v.x *= w; v.y *= w; v.z *= w; v.w *= w;
    red_add_v4(g_agg1 + (size_t)d * D_IN + lane * 4, v);
    if (lane == 0) atomicAdd(&g_cnt[d], 1.0f);
}

// ---------------- 1/max(cnt,1) ----------------
__global__ void inv_kernel() {
    int i = blockIdx.x * blockDim.x + threadIdx.x;
    if (i < N_NODES) g_inv[i] = 1.0f / fmaxf(g_cnt[i], 1.0f);
}

// ---------------- layer 1: h = relu((agg1*inv) @ Wl1^T + b1 + x @ Wr1^T) ----------------
#define L1_SMEM_FLOATS (2 * 128 * 129 + 2 * 16 * 128)
__global__ void layer1_kernel(const float* __restrict__ x,
                              const float* __restrict__ Wl,
                              const float* __restrict__ bl,
                              const float* __restrict__ Wr,
                              float* __restrict__ hout) {
    extern __shared__ float sm[];
    float* wl = sm;                  // [k][129]
    float* wr = sm + 128 * 129;
    float* fa = sm + 2 * 128 * 129;  // [16][128]  agg*inv
    float* fx = fa + 16 * 128;       // [16][128]  x
    int t = threadIdx.x;
    for (int i = t; i < 128 * 128; i += 512) {
        int j = i >> 7, k = i & 127;
        wl[k * 129 + j] = Wl[i];
        wr[k * 129 + j] = Wr[i];
    }
    int j = t & 127, grp = t >> 7;
    float bj = bl[j];
    __syncthreads();
    const int NT = N_NODES / 16;     // 6250, exact
    for (int tile = blockIdx.x; tile < NT; tile += gridDim.x) {
        int base = tile * 16;
        __syncthreads();
        for (int i = t; i < 16 * 128; i += 512) {
            int n = i >> 7, k = i & 127;
            fa[i] = g_agg1[(size_t)(base + n) * 128 + k] * g_inv[base + n];
            fx[i] = x[(size_t)(base + n) * 128 + k];
        }
        __syncthreads();
        float acc0 = bj, acc1 = bj, acc2 = bj, acc3 = bj;
        int nb = grp * 4 * 128;
        #pragma unroll 8
        for (int k = 0; k < 128; k += 4) {
            float wl0 = wl[(k + 0) * 129 + j], wl1 = wl[(k + 1) * 129 + j];
            float wl2 = wl[(k + 2) * 129 + j], wl3 = wl[(k + 3) * 129 + j];
            float wr0 = wr[(k + 0) * 129 + j], wr1 = wr[(k + 1) * 129 + j];
            float wr2 = wr[(k + 2) * 129 + j], wr3 = wr[(k + 3) * 129 + j];
            float4 a0 = *reinterpret_cast<const float4*>(&fa[nb +   0 + k]);
            float4 a1 = *reinterpret_cast<const float4*>(&fa[nb + 128 + k]);
            float4 a2 = *reinterpret_cast<const float4*>(&fa[nb + 256 + k]);
            float4 a3 = *reinterpret_cast<const float4*>(&fa[nb + 384 + k]);
            float4 x0 = *reinterpret_cast<const float4*>(&fx[nb +   0 + k]);
            float4 x1 = *reinterpret_cast<const float4*>(&fx[nb + 128 + k]);
            float4 x2 = *reinterpret_cast<const float4*>(&fx[nb + 256 + k]);
            float4 x3 = *reinterpret_cast<const float4*>(&fx[nb + 384 + k]);
            acc0 = fmaf(a0.x, wl0, fmaf(a0.y, wl1, fmaf(a0.z, wl2, fmaf(a0.w, wl3, acc0))));
            acc0 = fmaf(x0.x, wr0, fmaf(x0.y, wr1, fmaf(x0.z, wr2, fmaf(x0.w, wr3, acc0))));
            acc1 = fmaf(a1.x, wl0, fmaf(a1.y, wl1, fmaf(a1.z, wl2, fmaf(a1.w, wl3, acc1))));
            acc1 = fmaf(x1.x, wr0, fmaf(x1.y, wr1, fmaf(x1.z, wr2, fmaf(x1.w, wr3, acc1))));
            acc2 = fmaf(a2.x, wl0, fmaf(a2.y, wl1, fmaf(a2.z, wl2, fmaf(a2.w, wl3, acc2))));
            acc2 = fmaf(x2.x, wr0, fmaf(x2.y, wr1, fmaf(x2.z, wr2, fmaf(x2.w, wr3, acc2))));
            acc3 = fmaf(a3.x, wl0, fmaf(a3.y, wl1, fmaf(a3.z, wl2, fmaf(a3.w, wl3, acc3))));
            acc3 = fmaf(x3.x, wr0, fmaf(x3.y, wr1, fmaf(x3.z, wr2, fmaf(x3.w, wr3, acc3))));
        }
        int n0 = base + grp * 4;
        hout[(size_t)(n0 + 0) * 128 + j] = fmaxf(acc0, 0.f);
        hout[(size_t)(n0 + 1) * 128 + j] = fmaxf(acc1, 0.f);
        hout[(size_t)(n0 + 2) * 128 + j] = fmaxf(acc2, 0.f);
        hout[(size_t)(n0 + 3) * 128 + j] = fmaxf(acc3, 0.f);
    }
}

// ---------------- t = h @ Wl2^T  (pre-transform so layer-2 scatter is 64-dim) ----------------
#define L2_SMEM_FLOATS (128 * 65 + 16 * 128)
__global__ void tmat_kernel(const float* __restrict__ h,
                            const float* __restrict__ Wl2) {
    extern __shared__ float sm[];
    float* wl = sm;                // [k][65]
    float* fh = sm + 128 * 65;     // [16][128]
    int t = threadIdx.x;           // 512
    for (int i = t; i < 64 * 128; i += 512) {
        int j = i >> 7, k = i & 127;
        wl[k * 65 + j] = Wl2[i];
    }
    int j = t & 63, grp = t >> 6;  // 8 groups x 2 nodes
    __syncthreads();
    const int NT = N_NODES / 16;
    for (int tile = blockIdx.x; tile < NT; tile += gridDim.x) {
        int base = tile * 16;
        __syncthreads();
        for (int i = t; i < 16 * 128; i += 512)
            fh[i] = h[(size_t)base * 128 + i];
        __syncthreads();
        float acc0 = 0.f, acc1 = 0.f;
        int nb = grp * 2 * 128;
        #pragma unroll 8
        for (int k = 0; k < 128; k += 4) {
            float w0 = wl[(k + 0) * 65 + j], w1 = wl[(k + 1) * 65 + j];
            float w2 = wl[(k + 2) * 65 + j], w3 = wl[(k + 3) * 65 + j];
            float4 a0 = *reinterpret_cast<const float4*>(&fh[nb + k]);
            float4 a1 = *reinterpret_cast<const float4*>(&fh[nb + 128 + k]);
            acc0 = fmaf(a0.x, w0, fmaf(a0.y, w1, fmaf(a0.z, w2, fmaf(a0.w, w3, acc0))));
            acc1 = fmaf(a1.x, w0, fmaf(a1.y, w1, fmaf(a1.z, w2, fmaf(a1.w, w3, acc1))));
        }
        int n0 = base + grp * 2;
        g_t[(size_t)(n0 + 0) * 64 + j] = acc0;
        g_t[(size_t)(n0 + 1) * 64 + j] = acc1;
    }
}

// ---------------- layer-2 scatter: agg2[dst] += t[src]*w (64-dim, 16 threads/edge) ----------------
__global__ void scatter2_kernel(const void* __restrict__ ei,
                                const float* __restrict__ ew) {
    int gt = blockIdx.x * blockDim.x + threadIdx.x;
    int e = gt >> 4;
    if (e >= N_EDGES) return;
    int sub = gt & 15;
    int mode64 = g_idx64;
    int s = load_idx(ei, e, 0, mode64);
    int d = load_idx(ei, e, 1, mode64);
    if ((unsigned)s >= N_NODES || (unsigned)d >= N_NODES) return;  // guard
    float w = __ldg(&ew[e]);
    float4 v = __ldg(reinterpret_cast<const float4*>(g_t + (size_t)s * 64) + sub);
    v.x *= w; v.y *= w; v.z *= w; v.w *= w;
    red_add_v4(g_agg2 + (size_t)d * 64 + sub * 4, v);
}

// ---------------- logits = agg2*inv + b2 + h @ Wr2^T ----------------
__global__ void logits_kernel(const float* __restrict__ h,
                              const float* __restrict__ Wr2,
                              const float* __restrict__ b2,
                              float* __restrict__ out) {
    extern __shared__ float sm[];
    float* wr = sm;                // [k][65]
    float* fh = sm + 128 * 65;     // [16][128]
    int t = threadIdx.x;
    for (int i = t; i < 64 * 128; i += 512) {
        int j = i >> 7, k = i & 127;
        wr[k * 65 + j] = Wr2[i];
    }
    int j = t & 63, grp = t >> 6;
    float bj = b2[j];
    __syncthreads();
    const int NT = N_NODES / 16;
    for (int tile = blockIdx.x; tile < NT; tile += gridDim.x) {
        int base = tile * 16;
        __syncthreads();
        for (int i = t; i < 16 * 128; i += 512)
            fh[i] = h[(size_t)base * 128 + i];
        __syncthreads();
        float acc0 = 0.f, acc1 = 0.f;
        int nb = grp * 2 * 128;
        #pragma unroll 8
        for (int k = 0; k < 128; k += 4) {
            float w0 = wr[(k + 0) * 65 + j], w1 = wr[(k + 1) * 65 + j];
            float w2 = wr[(k + 2) * 65 + j], w3 = wr[(k + 3) * 65 + j];
            float4 a0 = *reinterpret_cast<const float4*>(&fh[nb + k]);
            float4 a1 = *reinterpret_cast<const float4*>(&fh[nb + 128 + k]);
            acc0 = fmaf(a0.x, w0, fmaf(a0.y, w1, fmaf(a0.z, w2, fmaf(a0.w, w3, acc0))));
            acc1 = fmaf(a1.x, w0, fmaf(a1.y, w1, fmaf(a1.z, w2, fmaf(a1.w, w3, acc1))));
        }
        int n0 = base + grp * 2;
        out[(size_t)(n0 + 0) * 64 + j] =
            acc0 + g_agg2[(size_t)(n0 + 0) * 64 + j] * g_inv[n0 + 0] + bj;
        out[(size_t)(n0 + 1) * 64 + j] =
            acc1 + g_agg2[(size_t)(n0 + 1) * 64 + j] * g_inv[n0 + 1] + bj;
    }
}

// ---------------- launch ----------------
extern "C" void kernel_launch(void* const* d_in, const int* in_sizes, int n_in,
                              void* d_out, int out_size) {
    (void)in_sizes; (void)n_in;
    const float* x   = (const float*)d_in[0];
    const void*  ei  = d_in[1];                 // int32 or int64, detected on device
    const float* ew  = (const float*)d_in[2];
    const float* Wl1 = (const float*)d_in[3];
    const float* bl1 = (const float*)d_in[4];
    const float* Wr1 = (const float*)d_in[5];
    const float* Wl2 = (const float*)d_in[6];
    const float* bl2 = (const float*)d_in[7];
    const float* Wr2 = (const float*)d_in[8];

    // Output layout: full tuple (h then logits) if d_out is large enough,
    // otherwise logits only (h kept in device scratch).
    float* hptr;
    float* lptr;
    const size_t full = (size_t)N_NODES * (D_HID + D_OUT);
    if ((size_t)out_size >= full) {
        hptr = (float*)d_out;
        lptr = hptr + (size_t)N_NODES * D_HID;
    } else {
        void* sym = nullptr;
        cudaGetSymbolAddress(&sym, g_h);
        hptr = (float*)sym;
        lptr = (float*)d_out;
    }

    cudaFuncSetAttribute(layer1_kernel,
                         cudaFuncAttributeMaxDynamicSharedMemorySize,
                         L1_SMEM_FLOATS * (int)sizeof(float));

    detect_kernel<<<1, 256>>>((const int*)ei);
    init_kernel<<<512, 256>>>();
    scatter1_kernel<<<N_EDGES / 8, 256>>>(x, ei, ew);        // 1 warp / edge
    inv_kernel<<<(N_NODES + 255) / 256, 256>>>();
    layer1_kernel<<<148, 512, L1_SMEM_FLOATS * sizeof(float)>>>(x, Wl1, bl1, Wr1, hptr);
    tmat_kernel<<<592, 512, L2_SMEM_FLOATS * sizeof(float)>>>(hptr, Wl2);
    scatter2_kernel<<<N_EDGES / 16, 256>>>(ei, ew);          // 16 threads / edge
    logits_kernel<<<592, 512, L2_SMEM_FLOATS * sizeof(float)>>>(hptr, Wr2, bl2, lptr);
}

// round 4
// speedup vs baseline: 1.3540x; 1.3540x over previous
#include <cuda_runtime.h>
#include <cstddef>

#define N_NODES 100000
#define N_EDGES 3200000
#define D_IN    128
#define D_HID   128
#define D_OUT   64

// ---------------- scratch (no allocation allowed) ----------------
__device__ __align__(16) float g_agg1[(size_t)N_NODES * D_IN];   // mean-agg of x
__device__ __align__(16) float g_t   [(size_t)N_NODES * D_OUT];  // h @ W_l2^T
__device__ __align__(16) float g_agg2[(size_t)N_NODES * D_OUT];  // mean-agg of t
__device__ __align__(16) float g_h   [(size_t)N_NODES * D_HID];  // fallback h storage
__device__ int  g_deg [N_NODES];
__device__ int  g_off [N_NODES + 1];
__device__ int  g_pos [N_NODES];
__device__ __align__(16) int2 g_edge[N_EDGES];                   // (src, w-bits), dst-grouped
__device__ int  g_idx64;   // 1 if edge_index is int64, 0 if int32

// ---------------- f32x2 helpers ----------------
__device__ __forceinline__ unsigned long long ffma2(unsigned long long a,
                                                    unsigned long long b,
                                                    unsigned long long c) {
    unsigned long long d;
    asm("fma.rn.f32x2 %0, %1, %2, %3;" : "=l"(d) : "l"(a), "l"(b), "l"(c));
    return d;
}
__device__ __forceinline__ unsigned long long pack2(float lo, float hi) {
    unsigned long long d;
    asm("mov.b64 %0, {%1, %2};" : "=l"(d) : "f"(lo), "f"(hi));
    return d;
}
__device__ __forceinline__ void unpack2(unsigned long long d, float& lo, float& hi) {
    asm("mov.b64 {%0, %1}, %2;" : "=f"(lo), "=f"(hi) : "l"(d));
}

// Load edge endpoint #e (src if half==0, dst if half==1) honoring detected dtype.
__device__ __forceinline__ int load_idx(const void* ei, int e, int half, int mode64) {
    if (mode64) {
        long long v = __ldg(reinterpret_cast<const long long*>(ei) +
                            (size_t)half * N_EDGES + e);
        return (int)v;
    } else {
        return __ldg(reinterpret_cast<const int*>(ei) + (size_t)half * N_EDGES + e);
    }
}

// ---------------- dtype detection ----------------
__global__ void detect_kernel(const int* __restrict__ ei_words) {
    __shared__ int any_nonzero;
    if (threadIdx.x == 0) any_nonzero = 0;
    __syncthreads();
    int acc = 0;
    for (int i = threadIdx.x; i < 4096; i += blockDim.x)
        acc |= ei_words[2 * i + 1];
    if (acc) atomicOr(&any_nonzero, 1);
    __syncthreads();
    if (threadIdx.x == 0) g_idx64 = any_nonzero ? 0 : 1;
}

// ---------------- CSR build ----------------
__global__ void zero_deg_kernel() {
    int i = blockIdx.x * blockDim.x + threadIdx.x;
    if (i < N_NODES) g_deg[i] = 0;
}

__global__ void hist_kernel(const void* __restrict__ ei) {
    int e = blockIdx.x * blockDim.x + threadIdx.x;
    if (e >= N_EDGES) return;
    int mode64 = g_idx64;
    int d = load_idx(ei, e, 1, mode64);
    if ((unsigned)d < N_NODES) atomicAdd(&g_deg[d], 1);
}

#define SCAN_T 1024
__global__ void scan_kernel() {
    __shared__ int part[SCAN_T];
    int t = threadIdx.x;
    const int CH = (N_NODES + SCAN_T - 1) / SCAN_T;   // 98
    int lo = t * CH;
    int hi = lo + CH; if (hi > N_NODES) hi = N_NODES;
    if (lo > N_NODES) lo = N_NODES;
    int s = 0;
    for (int i = lo; i < hi; ++i) s += g_deg[i];
    part[t] = s;
    __syncthreads();
    for (int d = 1; d < SCAN_T; d <<= 1) {
        int v = (t >= d) ? part[t - d] : 0;
        __syncthreads();
        part[t] += v;
        __syncthreads();
    }
    int run = (t == 0) ? 0 : part[t - 1];             // exclusive
    for (int i = lo; i < hi; ++i) {
        int d = g_deg[i];
        g_off[i] = run;
        g_pos[i] = run;
        run += d;
    }
    if (t == SCAN_T - 1) g_off[N_NODES] = part[SCAN_T - 1];
}

__global__ void fill_kernel(const void* __restrict__ ei,
                            const float* __restrict__ ew) {
    int e = blockIdx.x * blockDim.x + threadIdx.x;
    if (e >= N_EDGES) return;
    int mode64 = g_idx64;
    int s = load_idx(ei, e, 0, mode64);
    int d = load_idx(ei, e, 1, mode64);
    if ((unsigned)s >= N_NODES || (unsigned)d >= N_NODES) return;
    int p = atomicAdd(&g_pos[d], 1);
    g_edge[p] = make_int2(s, __float_as_int(__ldg(&ew[e])));
}

// ---------------- gather1: agg1[n] = mean over in-edges of x[src]*w ----------------
// one warp per node; lane covers 4 consecutive features (float4)
__global__ void gather1_kernel(const float* __restrict__ x) {
    int n = (blockIdx.x * blockDim.x + threadIdx.x) >> 5;
    if (n >= N_NODES) return;
    int lane = threadIdx.x & 31;
    int off = g_off[n], end = g_off[n + 1];
    float4 acc = make_float4(0.f, 0.f, 0.f, 0.f);
    for (int i = off; i < end; ++i) {
        int2 e = __ldg(reinterpret_cast<const int2*>(g_edge) + i);
        float w = __int_as_float(e.y);
        float4 v = __ldg(reinterpret_cast<const float4*>(x + (size_t)e.x * D_IN) + lane);
        acc.x = fmaf(v.x, w, acc.x);
        acc.y = fmaf(v.y, w, acc.y);
        acc.z = fmaf(v.z, w, acc.z);
        acc.w = fmaf(v.w, w, acc.w);
    }
    float inv = 1.0f / fmaxf((float)(end - off), 1.0f);
    acc.x *= inv; acc.y *= inv; acc.z *= inv; acc.w *= inv;
    reinterpret_cast<float4*>(g_agg1 + (size_t)n * D_IN)[lane] = acc;
}

// ---------------- layer 1 (f32x2): h = relu(agg1 @ Wl1^T + b1 + x @ Wr1^T) ----------------
// 512 threads; jj = t&31 -> channels 4jj..4jj+3 ; grp = t>>5 -> 2 nodes of a 32-node tile.
// Weights transposed in smem [k][j] stride 132 (ull2 loads give packed channel pairs).
// Features duplicated {f,f} in smem once per tile.
#define L1_WPAD 132
#define L1_TILE 32
#define L1_SMEM_BYTES (2 * 128 * L1_WPAD * 4 + 2 * L1_TILE * 128 * 8)  // 200704
__global__ void layer1_kernel(const float* __restrict__ x,
                              const float* __restrict__ Wl,
                              const float* __restrict__ bl,
                              const float* __restrict__ Wr,
                              float* __restrict__ hout) {
    extern __shared__ float sm[];
    float* wlT = sm;                            // [128][132]
    float* wrT = sm + 128 * L1_WPAD;
    unsigned long long* fa = reinterpret_cast<unsigned long long*>(sm + 2 * 128 * L1_WPAD); // [32][128]
    unsigned long long* fx = fa + L1_TILE * 128;
    int t = threadIdx.x;
    for (int i = t; i < 128 * 128; i += 512) {
        int j = i >> 7, k = i & 127;
        wlT[k * L1_WPAD + j] = Wl[i];
        wrT[k * L1_WPAD + j] = Wr[i];
    }
    int jj = t & 31;          // channel quad
    int grp = t >> 5;         // node pair index (0..15)
    float b0 = bl[4 * jj + 0], b1 = bl[4 * jj + 1];
    float b2 = bl[4 * jj + 2], b3 = bl[4 * jj + 3];
    __syncthreads();
    const int NT = N_NODES / L1_TILE;           // 3125, exact
    for (int tile = blockIdx.x; tile < NT; tile += gridDim.x) {
        int base = tile * L1_TILE;
        __syncthreads();
        for (int i = t; i < L1_TILE * 128; i += 512) {
            int n = i >> 7, k = i & 127;
            float a = g_agg1[(size_t)(base + n) * 128 + k];
            float b = x[(size_t)(base + n) * 128 + k];
            fa[i] = pack2(a, a);
            fx[i] = pack2(b, b);
        }
        __syncthreads();
        int n0 = grp * 2, n1 = grp * 2 + 1;
        unsigned long long acc00 = pack2(b0, b1), acc01 = pack2(b2, b3);
        unsigned long long acc10 = acc00, acc11 = acc01;
        const unsigned long long* fan0 = fa + n0 * 128;
        const unsigned long long* fan1 = fa + n1 * 128;
        const unsigned long long* fxn0 = fx + n0 * 128;
        const unsigned long long* fxn1 = fx + n1 * 128;
        #pragma unroll 4
        for (int k = 0; k < 128; ++k) {
            ulonglong2 wl2 = *reinterpret_cast<const ulonglong2*>(&wlT[k * L1_WPAD + 4 * jj]);
            ulonglong2 wr2 = *reinterpret_cast<const ulonglong2*>(&wrT[k * L1_WPAD + 4 * jj]);
            unsigned long long a0 = fan0[k], a1 = fan1[k];
            unsigned long long x0 = fxn0[k], x1 = fxn1[k];
            acc00 = ffma2(wl2.x, a0, acc00);
            acc01 = ffma2(wl2.y, a0, acc01);
            acc10 = ffma2(wl2.x, a1, acc10);
            acc11 = ffma2(wl2.y, a1, acc11);
            acc00 = ffma2(wr2.x, x0, acc00);
            acc01 = ffma2(wr2.y, x0, acc01);
            acc10 = ffma2(wr2.x, x1, acc10);
            acc11 = ffma2(wr2.y, x1, acc11);
        }
        float4 o;
        unpack2(acc00, o.x, o.y); unpack2(acc01, o.z, o.w);
        o.x = fmaxf(o.x, 0.f); o.y = fmaxf(o.y, 0.f);
        o.z = fmaxf(o.z, 0.f); o.w = fmaxf(o.w, 0.f);
        *reinterpret_cast<float4*>(&hout[(size_t)(base + n0) * 128 + 4 * jj]) = o;
        unpack2(acc10, o.x, o.y); unpack2(acc11, o.z, o.w);
        o.x = fmaxf(o.x, 0.f); o.y = fmaxf(o.y, 0.f);
        o.z = fmaxf(o.z, 0.f); o.w = fmaxf(o.w, 0.f);
        *reinterpret_cast<float4*>(&hout[(size_t)(base + n1) * 128 + 4 * jj]) = o;
    }
}

// ---------------- t = h @ Wl2^T (scalar GEMM, proven) ----------------
#define L2_SMEM_FLOATS (128 * 65 + 16 * 128)
__global__ void tmat_kernel(const float* __restrict__ h,
                            const float* __restrict__ Wl2) {
    extern __shared__ float sm[];
    float* wl = sm;                // [k][65]
    float* fh = sm + 128 * 65;     // [16][128]
    int t = threadIdx.x;           // 512
    for (int i = t; i < 64 * 128; i += 512) {
        int j = i >> 7, k = i & 127;
        wl[k * 65 + j] = Wl2[i];
    }
    int j = t & 63, grp = t >> 6;
    __syncthreads();
    const int NT = N_NODES / 16;
    for (int tile = blockIdx.x; tile < NT; tile += gridDim.x) {
        int base = tile * 16;
        __syncthreads();
        for (int i = t; i < 16 * 128; i += 512)
            fh[i] = h[(size_t)base * 128 + i];
        __syncthreads();
        float acc0 = 0.f, acc1 = 0.f;
        int nb = grp * 2 * 128;
        #pragma unroll 8
        for (int k = 0; k < 128; k += 4) {
            float w0 = wl[(k + 0) * 65 + j], w1 = wl[(k + 1) * 65 + j];
            float w2 = wl[(k + 2) * 65 + j], w3 = wl[(k + 3) * 65 + j];
            float4 a0 = *reinterpret_cast<const float4*>(&fh[nb + k]);
            float4 a1 = *reinterpret_cast<const float4*>(&fh[nb + 128 + k]);
            acc0 = fmaf(a0.x, w0, fmaf(a0.y, w1, fmaf(a0.z, w2, fmaf(a0.w, w3, acc0))));
            acc1 = fmaf(a1.x, w0, fmaf(a1.y, w1, fmaf(a1.z, w2, fmaf(a1.w, w3, acc1))));
        }
        int n0 = base + grp * 2;
        g_t[(size_t)(n0 + 0) * 64 + j] = acc0;
        g_t[(size_t)(n0 + 1) * 64 + j] = acc1;
    }
}

// ---------------- gather2: agg2[n] = mean over in-edges of t[src]*w ----------------
// one warp per node; lane covers 2 features (float2)
__global__ void gather2_kernel() {
    int n = (blockIdx.x * blockDim.x + threadIdx.x) >> 5;
    if (n >= N_NODES) return;
    int lane = threadIdx.x & 31;
    int off = g_off[n], end = g_off[n + 1];
    float2 acc = make_float2(0.f, 0.f);
    for (int i = off; i < end; ++i) {
        int2 e = __ldg(reinterpret_cast<const int2*>(g_edge) + i);
        float w = __int_as_float(e.y);
        float2 v = __ldg(reinterpret_cast<const float2*>(g_t + (size_t)e.x * D_OUT) + lane);
        acc.x = fmaf(v.x, w, acc.x);
        acc.y = fmaf(v.y, w, acc.y);
    }
    float inv = 1.0f / fmaxf((float)(end - off), 1.0f);
    acc.x *= inv; acc.y *= inv;
    reinterpret_cast<float2*>(g_agg2 + (size_t)n * D_OUT)[lane] = acc;
}

// ---------------- logits = agg2 + b2 + h @ Wr2^T (agg2 already mean) ----------------
__global__ void logits_kernel(const float* __restrict__ h,
                              const float* __restrict__ Wr2,
                              const float* __restrict__ b2,
                              float* __restrict__ out) {
    extern __shared__ float sm[];
    float* wr = sm;                // [k][65]
    float* fh = sm + 128 * 65;     // [16][128]
    int t = threadIdx.x;
    for (int i = t; i < 64 * 128; i += 512) {
        int j = i >> 7, k = i & 127;
        wr[k * 65 + j] = Wr2[i];
    }
    int j = t & 63, grp = t >> 6;
    float bj = b2[j];
    __syncthreads();
    const int NT = N_NODES / 16;
    for (int tile = blockIdx.x; tile < NT; tile += gridDim.x) {
        int base = tile * 16;
        __syncthreads();
        for (int i = t; i < 16 * 128; i += 512)
            fh[i] = h[(size_t)base * 128 + i];
        __syncthreads();
        float acc0 = 0.f, acc1 = 0.f;
        int nb = grp * 2 * 128;
        #pragma unroll 8
        for (int k = 0; k < 128; k += 4) {
            float w0 = wr[(k + 0) * 65 + j], w1 = wr[(k + 1) * 65 + j];
            float w2 = wr[(k + 2) * 65 + j], w3 = wr[(k + 3) * 65 + j];
            float4 a0 = *reinterpret_cast<const float4*>(&fh[nb + k]);
            float4 a1 = *reinterpret_cast<const float4*>(&fh[nb + 128 + k]);
            acc0 = fmaf(a0.x, w0, fmaf(a0.y, w1, fmaf(a0.z, w2, fmaf(a0.w, w3, acc0))));
            acc1 = fmaf(a1.x, w0, fmaf(a1.y, w1, fmaf(a1.z, w2, fmaf(a1.w, w3, acc1))));
        }
        int n0 = base + grp * 2;
        out[(size_t)(n0 + 0) * 64 + j] = acc0 + g_agg2[(size_t)(n0 + 0) * 64 + j] + bj;
        out[(size_t)(n0 + 1) * 64 + j] = acc1 + g_agg2[(size_t)(n0 + 1) * 64 + j] + bj;
    }
}

// ---------------- launch ----------------
extern "C" void kernel_launch(void* const* d_in, const int* in_sizes, int n_in,
                              void* d_out, int out_size) {
    (void)in_sizes; (void)n_in;
    const float* x   = (const float*)d_in[0];
    const void*  ei  = d_in[1];                 // int32 or int64, detected on device
    const float* ew  = (const float*)d_in[2];
    const float* Wl1 = (const float*)d_in[3];
    const float* bl1 = (const float*)d_in[4];
    const float* Wr1 = (const float*)d_in[5];
    const float* Wl2 = (const float*)d_in[6];
    const float* bl2 = (const float*)d_in[7];
    const float* Wr2 = (const float*)d_in[8];

    float* hptr;
    float* lptr;
    const size_t full = (size_t)N_NODES * (D_HID + D_OUT);
    if ((size_t)out_size >= full) {
        hptr = (float*)d_out;
        lptr = hptr + (size_t)N_NODES * D_HID;
    } else {
        void* sym = nullptr;
        cudaGetSymbolAddress(&sym, g_h);
        hptr = (float*)sym;
        lptr = (float*)d_out;
    }

    cudaFuncSetAttribute(layer1_kernel,
                         cudaFuncAttributeMaxDynamicSharedMemorySize, L1_SMEM_BYTES);

    detect_kernel<<<1, 256>>>((const int*)ei);
    zero_deg_kernel<<<(N_NODES + 255) / 256, 256>>>();
    hist_kernel<<<N_EDGES / 256, 256>>>(ei);
    scan_kernel<<<1, SCAN_T>>>();
    fill_kernel<<<N_EDGES / 256, 256>>>(ei, ew);
    gather1_kernel<<<(N_NODES * 32 + 255) / 256, 256>>>(x);
    layer1_kernel<<<148, 512, L1_SMEM_BYTES>>>(x, Wl1, bl1, Wr1, hptr);
    tmat_kernel<<<296, 512, L2_SMEM_FLOATS * sizeof(float)>>>(hptr, Wl2);
    gather2_kernel<<<(N_NODES * 32 + 255) / 256, 256>>>();
    logits_kernel<<<296, 512, L2_SMEM_FLOATS * sizeof(float)>>>(hptr, Wr2, bl2, lptr);
}

// round 5
// speedup vs baseline: 1.6773x; 1.2388x over previous
#include <cuda_runtime.h>
#include <cstddef>

#define N_NODES 100000
#define N_EDGES 3200000
#define D_IN    128
#define D_HID   128
#define D_OUT   64
#define NBLK    391           // ceil(N_NODES / 256)

// ---------------- scratch (no allocation allowed) ----------------
__device__ __align__(16) float g_agg1[(size_t)N_NODES * D_IN];   // mean-agg of x
__device__ __align__(16) float g_t   [(size_t)N_NODES * D_OUT];  // h @ W_l2^T
__device__ __align__(16) float g_r   [(size_t)N_NODES * D_OUT];  // h @ W_r2^T + b2
__device__ __align__(16) float g_h   [(size_t)N_NODES * D_HID];  // fallback h storage
__device__ int  g_deg [N_NODES];
__device__ int  g_off [N_NODES + 1];
__device__ int  g_pos [N_NODES];
__device__ int  g_bsum[NBLK];
__device__ int  g_bpre[NBLK];
__device__ __align__(16) int2 g_edge[N_EDGES];                   // (src, w-bits), dst-grouped
__device__ int  g_idx64;   // 1 if edge_index is int64, 0 if int32

// ---------------- f32x2 helpers ----------------
__device__ __forceinline__ unsigned long long ffma2(unsigned long long a,
                                                    unsigned long long b,
                                                    unsigned long long c) {
    unsigned long long d;
    asm("fma.rn.f32x2 %0, %1, %2, %3;" : "=l"(d) : "l"(a), "l"(b), "l"(c));
    return d;
}
__device__ __forceinline__ unsigned long long pack2(float lo, float hi) {
    unsigned long long d;
    asm("mov.b64 %0, {%1, %2};" : "=l"(d) : "f"(lo), "f"(hi));
    return d;
}
__device__ __forceinline__ void unpack2(unsigned long long d, float& lo, float& hi) {
    asm("mov.b64 {%0, %1}, %2;" : "=f"(lo), "=f"(hi) : "l"(d));
}

// Load edge endpoint #e (src if half==0, dst if half==1) honoring detected dtype.
__device__ __forceinline__ int load_idx(const void* ei, int e, int half, int mode64) {
    if (mode64) {
        long long v = __ldg(reinterpret_cast<const long long*>(ei) +
                            (size_t)half * N_EDGES + e);
        return (int)v;
    } else {
        return __ldg(reinterpret_cast<const int*>(ei) + (size_t)half * N_EDGES + e);
    }
}

// ---------------- dtype detection ----------------
__global__ void detect_kernel(const int* __restrict__ ei_words) {
    __shared__ int any_nonzero;
    if (threadIdx.x == 0) any_nonzero = 0;
    __syncthreads();
    int acc = 0;
    for (int i = threadIdx.x; i < 4096; i += blockDim.x)
        acc |= ei_words[2 * i + 1];
    if (acc) atomicOr(&any_nonzero, 1);
    __syncthreads();
    if (threadIdx.x == 0) g_idx64 = any_nonzero ? 0 : 1;
}

// ---------------- CSR build ----------------
__global__ void zero_deg_kernel() {
    int i = blockIdx.x * blockDim.x + threadIdx.x;
    if (i < N_NODES) g_deg[i] = 0;
}

__global__ void hist_kernel(const void* __restrict__ ei) {
    int e = blockIdx.x * blockDim.x + threadIdx.x;
    if (e >= N_EDGES) return;
    int mode64 = g_idx64;
    int d = load_idx(ei, e, 1, mode64);
    if ((unsigned)d < N_NODES) atomicAdd(&g_deg[d], 1);
}

// 3-phase multi-block exclusive scan of g_deg -> g_off / g_pos
__global__ void blocksum_kernel() {
    __shared__ int s[256];
    int i = blockIdx.x * 256 + threadIdx.x;
    s[threadIdx.x] = (i < N_NODES) ? g_deg[i] : 0;
    __syncthreads();
    for (int d = 128; d > 0; d >>= 1) {
        if (threadIdx.x < d) s[threadIdx.x] += s[threadIdx.x + d];
        __syncthreads();
    }
    if (threadIdx.x == 0) g_bsum[blockIdx.x] = s[0];
}

__global__ void scan_bsum_kernel() {
    __shared__ int s[512];
    int t = threadIdx.x;
    int v = (t < NBLK) ? g_bsum[t] : 0;
    s[t] = v;
    __syncthreads();
    for (int d = 1; d < 512; d <<= 1) {
        int tmp = (t >= d) ? s[t - d] : 0;
        __syncthreads();
        s[t] += tmp;
        __syncthreads();
    }
    if (t < NBLK) g_bpre[t] = s[t] - v;      // exclusive
    if (t == 511) g_off[N_NODES] = s[511];   // total
}

__global__ void offsets_kernel() {
    __shared__ int s[256];
    int t = threadIdx.x;
    int i = blockIdx.x * 256 + t;
    int v = (i < N_NODES) ? g_deg[i] : 0;
    s[t] = v;
    __syncthreads();
    for (int d = 1; d < 256; d <<= 1) {
        int tmp = (t >= d) ? s[t - d] : 0;
        __syncthreads();
        s[t] += tmp;
        __syncthreads();
    }
    if (i < N_NODES) {
        int off = g_bpre[blockIdx.x] + s[t] - v;   // exclusive
        g_off[i] = off;
        g_pos[i] = off;
    }
}

__global__ void fill_kernel(const void* __restrict__ ei,
                            const float* __restrict__ ew) {
    int e = blockIdx.x * blockDim.x + threadIdx.x;
    if (e >= N_EDGES) return;
    int mode64 = g_idx64;
    int s = load_idx(ei, e, 0, mode64);
    int d = load_idx(ei, e, 1, mode64);
    if ((unsigned)s >= N_NODES || (unsigned)d >= N_NODES) return;
    int p = atomicAdd(&g_pos[d], 1);
    g_edge[p] = make_int2(s, __float_as_int(__ldg(&ew[e])));
}

// ---------------- gather1: agg1[n] = mean over in-edges of x[src]*w ----------------
__global__ void gather1_kernel(const float* __restrict__ x) {
    int n = (blockIdx.x * blockDim.x + threadIdx.x) >> 5;
    if (n >= N_NODES) return;
    int lane = threadIdx.x & 31;
    int off = g_off[n], end = g_off[n + 1];
    float4 acc = make_float4(0.f, 0.f, 0.f, 0.f);
    for (int i = off; i < end; ++i) {
        int2 e = __ldg(reinterpret_cast<const int2*>(g_edge) + i);
        float w = __int_as_float(e.y);
        float4 v = __ldg(reinterpret_cast<const float4*>(x + (size_t)e.x * D_IN) + lane);
        acc.x = fmaf(v.x, w, acc.x);
        acc.y = fmaf(v.y, w, acc.y);
        acc.z = fmaf(v.z, w, acc.z);
        acc.w = fmaf(v.w, w, acc.w);
    }
    float inv = 1.0f / fmaxf((float)(end - off), 1.0f);
    acc.x *= inv; acc.y *= inv; acc.z *= inv; acc.w *= inv;
    reinterpret_cast<float4*>(g_agg1 + (size_t)n * D_IN)[lane] = acc;
}

// ---------------- layer 1 (f32x2): h = relu(agg1 @ Wl1^T + b1 + x @ Wr1^T) ----------------
#define L1_WPAD 132
#define L1_TILE 32
#define L1_SMEM_BYTES (2 * 128 * L1_WPAD * 4 + 2 * L1_TILE * 128 * 8)  // 200704
__global__ void layer1_kernel(const float* __restrict__ x,
                              const float* __restrict__ Wl,
                              const float* __restrict__ bl,
                              const float* __restrict__ Wr,
                              float* __restrict__ hout) {
    extern __shared__ float sm[];
    float* wlT = sm;                            // [128][132]
    float* wrT = sm + 128 * L1_WPAD;
    unsigned long long* fa = reinterpret_cast<unsigned long long*>(sm + 2 * 128 * L1_WPAD); // [32][128]
    unsigned long long* fx = fa + L1_TILE * 128;
    int t = threadIdx.x;
    for (int i = t; i < 128 * 128; i += 512) {
        int j = i >> 7, k = i & 127;
        wlT[k * L1_WPAD + j] = Wl[i];
        wrT[k * L1_WPAD + j] = Wr[i];
    }
    int jj = t & 31;          // channel quad
    int grp = t >> 5;         // node pair index (0..15)
    float b0 = bl[4 * jj + 0], b1 = bl[4 * jj + 1];
    float b2 = bl[4 * jj + 2], b3 = bl[4 * jj + 3];
    __syncthreads();
    const int NT = N_NODES / L1_TILE;           // 3125, exact
    for (int tile = blockIdx.x; tile < NT; tile += gridDim.x) {
        int base = tile * L1_TILE;
        __syncthreads();
        for (int i = t; i < L1_TILE * 128; i += 512) {
            int n = i >> 7, k = i & 127;
            float a = g_agg1[(size_t)(base + n) * 128 + k];
            float b = x[(size_t)(base + n) * 128 + k];
            fa[i] = pack2(a, a);
            fx[i] = pack2(b, b);
        }
        __syncthreads();
        int n0 = grp * 2, n1 = grp * 2 + 1;
        unsigned long long acc00 = pack2(b0, b1), acc01 = pack2(b2, b3);
        unsigned long long acc10 = acc00, acc11 = acc01;
        const unsigned long long* fan0 = fa + n0 * 128;
        const unsigned long long* fan1 = fa + n1 * 128;
        const unsigned long long* fxn0 = fx + n0 * 128;
        const unsigned long long* fxn1 = fx + n1 * 128;
        #pragma unroll 4
        for (int k = 0; k < 128; ++k) {
            ulonglong2 wl2 = *reinterpret_cast<const ulonglong2*>(&wlT[k * L1_WPAD + 4 * jj]);
            ulonglong2 wr2 = *reinterpret_cast<const ulonglong2*>(&wrT[k * L1_WPAD + 4 * jj]);
            unsigned long long a0 = fan0[k], a1 = fan1[k];
            unsigned long long x0 = fxn0[k], x1 = fxn1[k];
            acc00 = ffma2(wl2.x, a0, acc00);
            acc01 = ffma2(wl2.y, a0, acc01);
            acc10 = ffma2(wl2.x, a1, acc10);
            acc11 = ffma2(wl2.y, a1, acc11);
            acc00 = ffma2(wr2.x, x0, acc00);
            acc01 = ffma2(wr2.y, x0, acc01);
            acc10 = ffma2(wr2.x, x1, acc10);
            acc11 = ffma2(wr2.y, x1, acc11);
        }
        float4 o;
        unpack2(acc00, o.x, o.y); unpack2(acc01, o.z, o.w);
        o.x = fmaxf(o.x, 0.f); o.y = fmaxf(o.y, 0.f);
        o.z = fmaxf(o.z, 0.f); o.w = fmaxf(o.w, 0.f);
        *reinterpret_cast<float4*>(&hout[(size_t)(base + n0) * 128 + 4 * jj]) = o;
        unpack2(acc10, o.x, o.y); unpack2(acc11, o.z, o.w);
        o.x = fmaxf(o.x, 0.f); o.y = fmaxf(o.y, 0.f);
        o.z = fmaxf(o.z, 0.f); o.w = fmaxf(o.w, 0.f);
        *reinterpret_cast<float4*>(&hout[(size_t)(base + n1) * 128 + 4 * jj]) = o;
    }
}

// ---------------- tmat2 (f32x2, fused): t = h@Wl2^T ; r = h@Wr2^T + b2 ----------------
// 512 threads; jj = t&15 -> channels 4jj..4jj+3 ; grp = t>>4 -> 1 node of a 32-node tile.
#define T2_WPAD 68
#define T2_TILE 32
#define T2_SMEM_BYTES (2 * 128 * T2_WPAD * 4 + T2_TILE * 128 * 8)  // 102400
__global__ void tmat2_kernel(const float* __restrict__ h,
                             const float* __restrict__ Wl2,
                             const float* __restrict__ Wr2,
                             const float* __restrict__ b2) {
    extern __shared__ float sm[];
    float* wlT = sm;                            // [128][68]
    float* wrT = sm + 128 * T2_WPAD;
    unsigned long long* fh = reinterpret_cast<unsigned long long*>(sm + 2 * 128 * T2_WPAD); // [32][128]
    int t = threadIdx.x;
    for (int i = t; i < 64 * 128; i += 512) {
        int j = i >> 7, k = i & 127;
        wlT[k * T2_WPAD + j] = Wl2[i];
        wrT[k * T2_WPAD + j] = Wr2[i];
    }
    int jj = t & 15;          // channel quad (0..15 -> 64 channels)
    int grp = t >> 4;         // node (0..31)
    float b0 = b2[4 * jj + 0], b1 = b2[4 * jj + 1];
    float b2v = b2[4 * jj + 2], b3 = b2[4 * jj + 3];
    __syncthreads();
    const int NT = N_NODES / T2_TILE;           // 3125
    for (int tile = blockIdx.x; tile < NT; tile += gridDim.x) {
        int base = tile * T2_TILE;
        __syncthreads();
        for (int i = t; i < T2_TILE * 128; i += 512) {
            float v = h[(size_t)base * 128 + i];
            fh[i] = pack2(v, v);
        }
        __syncthreads();
        unsigned long long tac0 = pack2(0.f, 0.f), tac1 = tac0;
        unsigned long long rac0 = pack2(b0, b1), rac1 = pack2(b2v, b3);
        const unsigned long long* fn = fh + grp * 128;
        #pragma unroll 4
        for (int k = 0; k < 128; ++k) {
            ulonglong2 wl2 = *reinterpret_cast<const ulonglong2*>(&wlT[k * T2_WPAD + 4 * jj]);
            ulonglong2 wr2 = *reinterpret_cast<const ulonglong2*>(&wrT[k * T2_WPAD + 4 * jj]);
            unsigned long long a = fn[k];
            tac0 = ffma2(wl2.x, a, tac0);
            tac1 = ffma2(wl2.y, a, tac1);
            rac0 = ffma2(wr2.x, a, rac0);
            rac1 = ffma2(wr2.y, a, rac1);
        }
        float4 o;
        int n = base + grp;
        unpack2(tac0, o.x, o.y); unpack2(tac1, o.z, o.w);
        *reinterpret_cast<float4*>(&g_t[(size_t)n * 64 + 4 * jj]) = o;
        unpack2(rac0, o.x, o.y); unpack2(rac1, o.z, o.w);
        *reinterpret_cast<float4*>(&g_r[(size_t)n * 64 + 4 * jj]) = o;
    }
}

// ---------------- gather2 + epilogue: out = mean-agg(t) + r ----------------
__global__ void gather2_kernel(float* __restrict__ out) {
    int n = (blockIdx.x * blockDim.x + threadIdx.x) >> 5;
    if (n >= N_NODES) return;
    int lane = threadIdx.x & 31;
    int off = g_off[n], end = g_off[n + 1];
    float2 acc = make_float2(0.f, 0.f);
    for (int i = off; i < end; ++i) {
        int2 e = __ldg(reinterpret_cast<const int2*>(g_edge) + i);
        float w = __int_as_float(e.y);
        float2 v = __ldg(reinterpret_cast<const float2*>(g_t + (size_t)e.x * D_OUT) + lane);
        acc.x = fmaf(v.x, w, acc.x);
        acc.y = fmaf(v.y, w, acc.y);
    }
    float inv = 1.0f / fmaxf((float)(end - off), 1.0f);
    float2 rv = *reinterpret_cast<const float2*>(g_r + (size_t)n * D_OUT + lane * 2);
    acc.x = fmaf(acc.x, inv, rv.x);
    acc.y = fmaf(acc.y, inv, rv.y);
    reinterpret_cast<float2*>(out + (size_t)n * D_OUT)[lane] = acc;
}

// ---------------- launch ----------------
extern "C" void kernel_launch(void* const* d_in, const int* in_sizes, int n_in,
                              void* d_out, int out_size) {
    (void)in_sizes; (void)n_in;
    const float* x   = (const float*)d_in[0];
    const void*  ei  = d_in[1];                 // int32 or int64, detected on device
    const float* ew  = (const float*)d_in[2];
    const float* Wl1 = (const float*)d_in[3];
    const float* bl1 = (const float*)d_in[4];
    const float* Wr1 = (const float*)d_in[5];
    const float* Wl2 = (const float*)d_in[6];
    const float* bl2 = (const float*)d_in[7];
    const float* Wr2 = (const float*)d_in[8];

    float* hptr;
    float* lptr;
    const size_t full = (size_t)N_NODES * (D_HID + D_OUT);
    if ((size_t)out_size >= full) {
        hptr = (float*)d_out;
        lptr = hptr + (size_t)N_NODES * D_HID;
    } else {
        void* sym = nullptr;
        cudaGetSymbolAddress(&sym, g_h);
        hptr = (float*)sym;
        lptr = (float*)d_out;
    }

    cudaFuncSetAttribute(layer1_kernel,
                         cudaFuncAttributeMaxDynamicSharedMemorySize, L1_SMEM_BYTES);
    cudaFuncSetAttribute(tmat2_kernel,
                         cudaFuncAttributeMaxDynamicSharedMemorySize, T2_SMEM_BYTES);

    detect_kernel<<<1, 256>>>((const int*)ei);
    zero_deg_kernel<<<NBLK, 256>>>();
    hist_kernel<<<N_EDGES / 256, 256>>>(ei);
    blocksum_kernel<<<NBLK, 256>>>();
    scan_bsum_kernel<<<1, 512>>>();
    offsets_kernel<<<NBLK, 256>>>();
    fill_kernel<<<N_EDGES / 256, 256>>>(ei, ew);
    gather1_kernel<<<(N_NODES * 32 + 255) / 256, 256>>>(x);
    layer1_kernel<<<148, 512, L1_SMEM_BYTES>>>(x, Wl1, bl1, Wr1, hptr);
    tmat2_kernel<<<296, 512, T2_SMEM_BYTES>>>(hptr, Wl2, Wr2, bl2);
    gather2_kernel<<<(N_NODES * 32 + 255) / 256, 256>>>(lptr);
}

// round 6
// speedup vs baseline: 1.9857x; 1.1839x over previous
#include <cuda_runtime.h>
#include <cstddef>

#define N_NODES 100000
#define N_EDGES 3200000
#define D_IN    128
#define D_HID   128
#define D_OUT   64
#define NBLK    391           // ceil(N_NODES / 256)

// ---------------- scratch (no allocation allowed) ----------------
__device__ __align__(16) float g_agg1[(size_t)N_NODES * D_IN];   // mean-agg of x
__device__ __align__(16) float g_t   [(size_t)N_NODES * D_OUT];  // h @ W_l2^T
__device__ __align__(16) float g_r   [(size_t)N_NODES * D_OUT];  // h @ W_r2^T + b2
__device__ __align__(16) float g_h   [(size_t)N_NODES * D_HID];  // fallback h storage
__device__ int  g_deg [N_NODES];
__device__ int  g_off [N_NODES + 1];
__device__ int  g_pos [N_NODES];
__device__ int  g_bsum[NBLK];
__device__ int  g_bpre[NBLK];
__device__ __align__(16) int2 g_edge[N_EDGES];                   // (src, w-bits), dst-grouped
__device__ int  g_idx64;   // 1 if edge_index is int64, 0 if int32

// ---------------- f32x2 helpers ----------------
__device__ __forceinline__ unsigned long long ffma2(unsigned long long a,
                                                    unsigned long long b,
                                                    unsigned long long c) {
    unsigned long long d;
    asm("fma.rn.f32x2 %0, %1, %2, %3;" : "=l"(d) : "l"(a), "l"(b), "l"(c));
    return d;
}
__device__ __forceinline__ void unpack2(unsigned long long d, float& lo, float& hi) {
    asm("mov.b64 {%0, %1}, %2;" : "=f"(lo), "=f"(hi) : "l"(d));
}

// Load edge endpoint #e (src if half==0, dst if half==1) honoring detected dtype.
__device__ __forceinline__ int load_idx(const void* ei, int e, int half, int mode64) {
    if (mode64) {
        long long v = __ldg(reinterpret_cast<const long long*>(ei) +
                            (size_t)half * N_EDGES + e);
        return (int)v;
    } else {
        return __ldg(reinterpret_cast<const int*>(ei) + (size_t)half * N_EDGES + e);
    }
}

// ---------------- dtype detection ----------------
__global__ void detect_kernel(const int* __restrict__ ei_words) {
    __shared__ int any_nonzero;
    if (threadIdx.x == 0) any_nonzero = 0;
    __syncthreads();
    int acc = 0;
    for (int i = threadIdx.x; i < 4096; i += blockDim.x)
        acc |= ei_words[2 * i + 1];
    if (acc) atomicOr(&any_nonzero, 1);
    __syncthreads();
    if (threadIdx.x == 0) g_idx64 = any_nonzero ? 0 : 1;
}

// ---------------- CSR build ----------------
__global__ void zero_deg_kernel() {
    int i = blockIdx.x * blockDim.x + threadIdx.x;
    if (i < N_NODES) g_deg[i] = 0;
}

__global__ void hist_kernel(const void* __restrict__ ei) {
    int e = blockIdx.x * blockDim.x + threadIdx.x;
    if (e >= N_EDGES) return;
    int mode64 = g_idx64;
    int d = load_idx(ei, e, 1, mode64);
    if ((unsigned)d < N_NODES) atomicAdd(&g_deg[d], 1);
}

__global__ void blocksum_kernel() {
    __shared__ int s[256];
    int i = blockIdx.x * 256 + threadIdx.x;
    s[threadIdx.x] = (i < N_NODES) ? g_deg[i] : 0;
    __syncthreads();
    for (int d = 128; d > 0; d >>= 1) {
        if (threadIdx.x < d) s[threadIdx.x] += s[threadIdx.x + d];
        __syncthreads();
    }
    if (threadIdx.x == 0) g_bsum[blockIdx.x] = s[0];
}

__global__ void scan_bsum_kernel() {
    __shared__ int s[512];
    int t = threadIdx.x;
    int v = (t < NBLK) ? g_bsum[t] : 0;
    s[t] = v;
    __syncthreads();
    for (int d = 1; d < 512; d <<= 1) {
        int tmp = (t >= d) ? s[t - d] : 0;
        __syncthreads();
        s[t] += tmp;
        __syncthreads();
    }
    if (t < NBLK) g_bpre[t] = s[t] - v;      // exclusive
    if (t == 511) g_off[N_NODES] = s[511];   // total
}

__global__ void offsets_kernel() {
    __shared__ int s[256];
    int t = threadIdx.x;
    int i = blockIdx.x * 256 + t;
    int v = (i < N_NODES) ? g_deg[i] : 0;
    s[t] = v;
    __syncthreads();
    for (int d = 1; d < 256; d <<= 1) {
        int tmp = (t >= d) ? s[t - d] : 0;
        __syncthreads();
        s[t] += tmp;
        __syncthreads();
    }
    if (i < N_NODES) {
        int off = g_bpre[blockIdx.x] + s[t] - v;   // exclusive
        g_off[i] = off;
        g_pos[i] = off;
    }
}

__global__ void fill_kernel(const void* __restrict__ ei,
                            const float* __restrict__ ew) {
    int e = blockIdx.x * blockDim.x + threadIdx.x;
    if (e >= N_EDGES) return;
    int mode64 = g_idx64;
    int s = load_idx(ei, e, 0, mode64);
    int d = load_idx(ei, e, 1, mode64);
    if ((unsigned)s >= N_NODES || (unsigned)d >= N_NODES) return;
    int p = atomicAdd(&g_pos[d], 1);
    g_edge[p] = make_int2(s, __float_as_int(__ldg(&ew[e])));
}

// ---------------- gather1: agg1[n] = mean over in-edges of x[src]*w ----------------
// one warp per node; lane covers 4 consecutive features; 4-way unrolled (MLP=4)
__global__ void gather1_kernel(const float* __restrict__ x) {
    int n = (blockIdx.x * blockDim.x + threadIdx.x) >> 5;
    if (n >= N_NODES) return;
    int lane = threadIdx.x & 31;
    int off = g_off[n], end = g_off[n + 1];
    float4 a0 = make_float4(0.f, 0.f, 0.f, 0.f);
    float4 a1 = a0, a2 = a0, a3 = a0;
    int i = off;
    for (; i + 4 <= end; i += 4) {
        int2 e0 = __ldg(reinterpret_cast<const int2*>(g_edge) + i + 0);
        int2 e1 = __ldg(reinterpret_cast<const int2*>(g_edge) + i + 1);
        int2 e2 = __ldg(reinterpret_cast<const int2*>(g_edge) + i + 2);
        int2 e3 = __ldg(reinterpret_cast<const int2*>(g_edge) + i + 3);
        float4 v0 = __ldg(reinterpret_cast<const float4*>(x + (size_t)e0.x * D_IN) + lane);
        float4 v1 = __ldg(reinterpret_cast<const float4*>(x + (size_t)e1.x * D_IN) + lane);
        float4 v2 = __ldg(reinterpret_cast<const float4*>(x + (size_t)e2.x * D_IN) + lane);
        float4 v3 = __ldg(reinterpret_cast<const float4*>(x + (size_t)e3.x * D_IN) + lane);
        float w0 = __int_as_float(e0.y), w1 = __int_as_float(e1.y);
        float w2 = __int_as_float(e2.y), w3 = __int_as_float(e3.y);
        a0.x = fmaf(v0.x, w0, a0.x); a0.y = fmaf(v0.y, w0, a0.y);
        a0.z = fmaf(v0.z, w0, a0.z); a0.w = fmaf(v0.w, w0, a0.w);
        a1.x = fmaf(v1.x, w1, a1.x); a1.y = fmaf(v1.y, w1, a1.y);
        a1.z = fmaf(v1.z, w1, a1.z); a1.w = fmaf(v1.w, w1, a1.w);
        a2.x = fmaf(v2.x, w2, a2.x); a2.y = fmaf(v2.y, w2, a2.y);
        a2.z = fmaf(v2.z, w2, a2.z); a2.w = fmaf(v2.w, w2, a2.w);
        a3.x = fmaf(v3.x, w3, a3.x); a3.y = fmaf(v3.y, w3, a3.y);
        a3.z = fmaf(v3.z, w3, a3.z); a3.w = fmaf(v3.w, w3, a3.w);
    }
    for (; i < end; ++i) {
        int2 e = __ldg(reinterpret_cast<const int2*>(g_edge) + i);
        float w = __int_as_float(e.y);
        float4 v = __ldg(reinterpret_cast<const float4*>(x + (size_t)e.x * D_IN) + lane);
        a0.x = fmaf(v.x, w, a0.x); a0.y = fmaf(v.y, w, a0.y);
        a0.z = fmaf(v.z, w, a0.z); a0.w = fmaf(v.w, w, a0.w);
    }
    a0.x += a1.x + a2.x + a3.x;
    a0.y += a1.y + a2.y + a3.y;
    a0.z += a1.z + a2.z + a3.z;
    a0.w += a1.w + a2.w + a3.w;
    float inv = 1.0f / fmaxf((float)(end - off), 1.0f);
    a0.x *= inv; a0.y *= inv; a0.z *= inv; a0.w *= inv;
    reinterpret_cast<float4*>(g_agg1 + (size_t)n * D_IN)[lane] = a0;
}

// ---------------- layer 1 (f32x2, K-packed): h = relu(agg1@Wl1^T + b1 + x@Wr1^T) ----------
// 512 threads. j = t&127 -> output channel; grp = t>>7 -> 8 nodes of a 32-node tile.
// Weights kept NATIVE [j][k] layout in smem (stride 132, conflict-free LDS.128).
// Features natural {f_k, f_k+1} pairs; acc halves = even-k/odd-k partials, hadd at end.
#define L1_WPAD 132
#define L1_TILE 32
#define L1_SMEM_BYTES (2 * 128 * L1_WPAD * 4 + 2 * L1_TILE * 128 * 4)  // 167936
__global__ void layer1_kernel(const float* __restrict__ x,
                              const float* __restrict__ Wl,
                              const float* __restrict__ bl,
                              const float* __restrict__ Wr,
                              float* __restrict__ hout) {
    extern __shared__ float sm[];
    float* wl = sm;                             // [128][132] native [j][k]
    float* wr = sm + 128 * L1_WPAD;
    float* fa = sm + 2 * 128 * L1_WPAD;         // [32][128]
    float* fx = fa + L1_TILE * 128;
    int t = threadIdx.x;
    for (int i = t; i < 128 * 128; i += 512) {
        int j = i >> 7, k = i & 127;
        wl[j * L1_WPAD + k] = Wl[i];
        wr[j * L1_WPAD + k] = Wr[i];
    }
    int j = t & 127;
    int grp = t >> 7;                           // 0..3 -> nodes grp*8 .. grp*8+7
    float bj = bl[j];
    __syncthreads();
    const int NT = N_NODES / L1_TILE;           // 3125, exact
    for (int tile = blockIdx.x; tile < NT; tile += gridDim.x) {
        int base = tile * L1_TILE;
        __syncthreads();
        for (int i = t; i < L1_TILE * 128; i += 512) {
            int n = i >> 7, k = i & 127;
            fa[i] = g_agg1[(size_t)(base + n) * 128 + k];
            fx[i] = x[(size_t)(base + n) * 128 + k];
        }
        __syncthreads();
        unsigned long long acc[8];
        #pragma unroll
        for (int n = 0; n < 8; ++n) acc[n] = 0ull;
        const float* fan = fa + grp * 8 * 128;
        const float* fxn = fx + grp * 8 * 128;
        const float* wlj = wl + j * L1_WPAD;
        const float* wrj = wr + j * L1_WPAD;
        #pragma unroll 4
        for (int k = 0; k < 128; k += 4) {
            ulonglong2 w_l = *reinterpret_cast<const ulonglong2*>(wlj + k);
            ulonglong2 w_r = *reinterpret_cast<const ulonglong2*>(wrj + k);
            #pragma unroll
            for (int n = 0; n < 8; ++n) {
                ulonglong2 f_a = *reinterpret_cast<const ulonglong2*>(fan + n * 128 + k);
                ulonglong2 f_x = *reinterpret_cast<const ulonglong2*>(fxn + n * 128 + k);
                acc[n] = ffma2(w_l.x, f_a.x, acc[n]);
                acc[n] = ffma2(w_l.y, f_a.y, acc[n]);
                acc[n] = ffma2(w_r.x, f_x.x, acc[n]);
                acc[n] = ffma2(w_r.y, f_x.y, acc[n]);
            }
        }
        #pragma unroll
        for (int n = 0; n < 8; ++n) {
            float lo, hi;
            unpack2(acc[n], lo, hi);
            float v = fmaxf(lo + hi + bj, 0.f);
            hout[(size_t)(base + grp * 8 + n) * 128 + j] = v;
        }
    }
}

// ---------------- tmat2 (f32x2, K-packed, fused): t = h@Wl2^T ; r = h@Wr2^T + b2 --------
// 512 threads. j = t&63 -> channel; grp = t>>6 -> 4 nodes of a 32-node tile.
#define T2_WPAD 132
#define T2_TILE 32
#define T2_SMEM_BYTES (2 * 64 * T2_WPAD * 4 + T2_TILE * 128 * 4)  // 83968
__global__ void tmat2_kernel(const float* __restrict__ h,
                             const float* __restrict__ Wl2,
                             const float* __restrict__ Wr2,
                             const float* __restrict__ b2) {
    extern __shared__ float sm[];
    float* wl = sm;                             // [64][132] native [j][k]
    float* wr = sm + 64 * T2_WPAD;
    float* fh = sm + 2 * 64 * T2_WPAD;          // [32][128]
    int t = threadIdx.x;
    for (int i = t; i < 64 * 128; i += 512) {
        int j = i >> 7, k = i & 127;
        wl[j * T2_WPAD + k] = Wl2[i];
        wr[j * T2_WPAD + k] = Wr2[i];
    }
    int j = t & 63;
    int grp = t >> 6;                           // 0..7 -> nodes grp*4 .. grp*4+3
    float bj = b2[j];
    __syncthreads();
    const int NT = N_NODES / T2_TILE;           // 3125
    for (int tile = blockIdx.x; tile < NT; tile += gridDim.x) {
        int base = tile * T2_TILE;
        __syncthreads();
        for (int i = t; i < T2_TILE * 128; i += 512)
            fh[i] = h[(size_t)base * 128 + i];
        __syncthreads();
        unsigned long long tac[4], rac[4];
        #pragma unroll
        for (int n = 0; n < 4; ++n) { tac[n] = 0ull; rac[n] = 0ull; }
        const float* fn = fh + grp * 4 * 128;
        const float* wlj = wl + j * T2_WPAD;
        const float* wrj = wr + j * T2_WPAD;
        #pragma unroll 4
        for (int k = 0; k < 128; k += 4) {
            ulonglong2 w_l = *reinterpret_cast<const ulonglong2*>(wlj + k);
            ulonglong2 w_r = *reinterpret_cast<const ulonglong2*>(wrj + k);
            #pragma unroll
            for (int n = 0; n < 4; ++n) {
                ulonglong2 f = *reinterpret_cast<const ulonglong2*>(fn + n * 128 + k);
                tac[n] = ffma2(w_l.x, f.x, tac[n]);
                tac[n] = ffma2(w_l.y, f.y, tac[n]);
                rac[n] = ffma2(w_r.x, f.x, rac[n]);
                rac[n] = ffma2(w_r.y, f.y, rac[n]);
            }
        }
        #pragma unroll
        for (int n = 0; n < 4; ++n) {
            int node = base + grp * 4 + n;
            float lo, hi;
            unpack2(tac[n], lo, hi);
            g_t[(size_t)node * 64 + j] = lo + hi;
            unpack2(rac[n], lo, hi);
            g_r[(size_t)node * 64 + j] = lo + hi + bj;
        }
    }
}

// ---------------- gather2 + epilogue: out = mean-agg(t) + r (4-way unrolled) ----------
__global__ void gather2_kernel(float* __restrict__ out) {
    int n = (blockIdx.x * blockDim.x + threadIdx.x) >> 5;
    if (n >= N_NODES) return;
    int lane = threadIdx.x & 31;
    int off = g_off[n], end = g_off[n + 1];
    float2 a0 = make_float2(0.f, 0.f), a1 = a0, a2 = a0, a3 = a0;
    int i = off;
    for (; i + 4 <= end; i += 4) {
        int2 e0 = __ldg(reinterpret_cast<const int2*>(g_edge) + i + 0);
        int2 e1 = __ldg(reinterpret_cast<const int2*>(g_edge) + i + 1);
        int2 e2 = __ldg(reinterpret_cast<const int2*>(g_edge) + i + 2);
        int2 e3 = __ldg(reinterpret_cast<const int2*>(g_edge) + i + 3);
        float2 v0 = __ldg(reinterpret_cast<const float2*>(g_t + (size_t)e0.x * D_OUT) + lane);
        float2 v1 = __ldg(reinterpret_cast<const float2*>(g_t + (size_t)e1.x * D_OUT) + lane);
        float2 v2 = __ldg(reinterpret_cast<const float2*>(g_t + (size_t)e2.x * D_OUT) + lane);
        float2 v3 = __ldg(reinterpret_cast<const float2*>(g_t + (size_t)e3.x * D_OUT) + lane);
        float w0 = __int_as_float(e0.y), w1 = __int_as_float(e1.y);
        float w2 = __int_as_float(e2.y), w3 = __int_as_float(e3.y);
        a0.x = fmaf(v0.x, w0, a0.x); a0.y = fmaf(v0.y, w0, a0.y);
        a1.x = fmaf(v1.x, w1, a1.x); a1.y = fmaf(v1.y, w1, a1.y);
        a2.x = fmaf(v2.x, w2, a2.x); a2.y = fmaf(v2.y, w2, a2.y);
        a3.x = fmaf(v3.x, w3, a3.x); a3.y = fmaf(v3.y, w3, a3.y);
    }
    for (; i < end; ++i) {
        int2 e = __ldg(reinterpret_cast<const int2*>(g_edge) + i);
        float w = __int_as_float(e.y);
        float2 v = __ldg(reinterpret_cast<const float2*>(g_t + (size_t)e.x * D_OUT) + lane);
        a0.x = fmaf(v.x, w, a0.x); a0.y = fmaf(v.y, w, a0.y);
    }
    a0.x += a1.x + a2.x + a3.x;
    a0.y += a1.y + a2.y + a3.y;
    float inv = 1.0f / fmaxf((float)(end - off), 1.0f);
    float2 rv = *reinterpret_cast<const float2*>(g_r + (size_t)n * D_OUT + lane * 2);
    a0.x = fmaf(a0.x, inv, rv.x);
    a0.y = fmaf(a0.y, inv, rv.y);
    reinterpret_cast<float2*>(out + (size_t)n * D_OUT)[lane] = a0;
}

// ---------------- launch ----------------
extern "C" void kernel_launch(void* const* d_in, const int* in_sizes, int n_in,
                              void* d_out, int out_size) {
    (void)in_sizes; (void)n_in;
    const float* x   = (const float*)d_in[0];
    const void*  ei  = d_in[1];                 // int32 or int64, detected on device
    const float* ew  = (const float*)d_in[2];
    const float* Wl1 = (const float*)d_in[3];
    const float* bl1 = (const float*)d_in[4];
    const float* Wr1 = (const float*)d_in[5];
    const float* Wl2 = (const float*)d_in[6];
    const float* bl2 = (const float*)d_in[7];
    const float* Wr2 = (const float*)d_in[8];

    float* hptr;
    float* lptr;
    const size_t full = (size_t)N_NODES * (D_HID + D_OUT);
    if ((size_t)out_size >= full) {
        hptr = (float*)d_out;
        lptr = hptr + (size_t)N_NODES * D_HID;
    } else {
        void* sym = nullptr;
        cudaGetSymbolAddress(&sym, g_h);
        hptr = (float*)sym;
        lptr = (float*)d_out;
    }

    cudaFuncSetAttribute(layer1_kernel,
                         cudaFuncAttributeMaxDynamicSharedMemorySize, L1_SMEM_BYTES);
    cudaFuncSetAttribute(tmat2_kernel,
                         cudaFuncAttributeMaxDynamicSharedMemorySize, T2_SMEM_BYTES);

    detect_kernel<<<1, 256>>>((const int*)ei);
    zero_deg_kernel<<<NBLK, 256>>>();
    hist_kernel<<<N_EDGES / 256, 256>>>(ei);
    blocksum_kernel<<<NBLK, 256>>>();
    scan_bsum_kernel<<<1, 512>>>();
    offsets_kernel<<<NBLK, 256>>>();
    fill_kernel<<<N_EDGES / 256, 256>>>(ei, ew);
    gather1_kernel<<<(N_NODES * 32 + 255) / 256, 256>>>(x);
    layer1_kernel<<<148, 512, L1_SMEM_BYTES>>>(x, Wl1, bl1, Wr1, hptr);
    tmat2_kernel<<<296, 512, T2_SMEM_BYTES>>>(hptr, Wl2, Wr2, bl2);
    gather2_kernel<<<(N_NODES * 32 + 255) / 256, 256>>>(lptr);
}

// round 7
// speedup vs baseline: 2.2821x; 1.1493x over previous
#include <cuda_runtime.h>
#include <cstddef>

#define N_NODES 100000
#define N_EDGES 3200000
#define D_IN    128
#define D_HID   128
#define D_OUT   64
#define NBLK    391           // ceil(N_NODES / 256)

// ---------------- scratch (no allocation allowed) ----------------
__device__ __align__(16) float g_agg1[(size_t)N_NODES * D_IN];   // mean-agg of x
__device__ __align__(16) float g_t   [(size_t)N_NODES * D_OUT];  // h @ W_l2^T
__device__ __align__(16) float g_r   [(size_t)N_NODES * D_OUT];  // h @ W_r2^T + b2
__device__ __align__(16) float g_h   [(size_t)N_NODES * D_HID];  // fallback h storage
__device__ int  g_deg [N_NODES];
__device__ int  g_off [N_NODES + 1];
__device__ int  g_pos [N_NODES];
__device__ int  g_bsum[NBLK];
__device__ int  g_bpre[NBLK];
__device__ __align__(16) int2 g_edge[N_EDGES];                   // (src, w-bits), dst-grouped
__device__ int  g_idx64;   // 1 if edge_index is int64, 0 if int32

// ---------------- f32x2 helpers ----------------
__device__ __forceinline__ unsigned long long ffma2(unsigned long long a,
                                                    unsigned long long b,
                                                    unsigned long long c) {
    unsigned long long d;
    asm("fma.rn.f32x2 %0, %1, %2, %3;" : "=l"(d) : "l"(a), "l"(b), "l"(c));
    return d;
}
__device__ __forceinline__ void unpack2(unsigned long long d, float& lo, float& hi) {
    asm("mov.b64 {%0, %1}, %2;" : "=f"(lo), "=f"(hi) : "l"(d));
}

// Load edge endpoint #e (src if half==0, dst if half==1) honoring detected dtype.
__device__ __forceinline__ int load_idx(const void* ei, int e, int half, int mode64) {
    if (mode64) {
        long long v = __ldg(reinterpret_cast<const long long*>(ei) +
                            (size_t)half * N_EDGES + e);
        return (int)v;
    } else {
        return __ldg(reinterpret_cast<const int*>(ei) + (size_t)half * N_EDGES + e);
    }
}

// ---------------- dtype detection ----------------
__global__ void detect_kernel(const int* __restrict__ ei_words) {
    __shared__ int any_nonzero;
    if (threadIdx.x == 0) any_nonzero = 0;
    __syncthreads();
    int acc = 0;
    for (int i = threadIdx.x; i < 4096; i += blockDim.x)
        acc |= ei_words[2 * i + 1];
    if (acc) atomicOr(&any_nonzero, 1);
    __syncthreads();
    if (threadIdx.x == 0) g_idx64 = any_nonzero ? 0 : 1;
}

// ---------------- CSR build ----------------
__global__ void zero_deg_kernel() {
    int i = blockIdx.x * blockDim.x + threadIdx.x;
    if (i < N_NODES) g_deg[i] = 0;
}

__global__ void hist_kernel(const void* __restrict__ ei) {
    int e = blockIdx.x * blockDim.x + threadIdx.x;
    if (e >= N_EDGES) return;
    int mode64 = g_idx64;
    int d = load_idx(ei, e, 1, mode64);
    if ((unsigned)d < N_NODES) atomicAdd(&g_deg[d], 1);
}

__global__ void blocksum_kernel() {
    __shared__ int s[256];
    int i = blockIdx.x * 256 + threadIdx.x;
    s[threadIdx.x] = (i < N_NODES) ? g_deg[i] : 0;
    __syncthreads();
    for (int d = 128; d > 0; d >>= 1) {
        if (threadIdx.x < d) s[threadIdx.x] += s[threadIdx.x + d];
        __syncthreads();
    }
    if (threadIdx.x == 0) g_bsum[blockIdx.x] = s[0];
}

__global__ void scan_bsum_kernel() {
    __shared__ int s[512];
    int t = threadIdx.x;
    int v = (t < NBLK) ? g_bsum[t] : 0;
    s[t] = v;
    __syncthreads();
    for (int d = 1; d < 512; d <<= 1) {
        int tmp = (t >= d) ? s[t - d] : 0;
        __syncthreads();
        s[t] += tmp;
        __syncthreads();
    }
    if (t < NBLK) g_bpre[t] = s[t] - v;      // exclusive
    if (t == 511) g_off[N_NODES] = s[511];   // total
}

__global__ void offsets_kernel() {
    __shared__ int s[256];
    int t = threadIdx.x;
    int i = blockIdx.x * 256 + t;
    int v = (i < N_NODES) ? g_deg[i] : 0;
    s[t] = v;
    __syncthreads();
    for (int d = 1; d < 256; d <<= 1) {
        int tmp = (t >= d) ? s[t - d] : 0;
        __syncthreads();
        s[t] += tmp;
        __syncthreads();
    }
    if (i < N_NODES) {
        int off = g_bpre[blockIdx.x] + s[t] - v;   // exclusive
        g_off[i] = off;
        g_pos[i] = off;
    }
}

__global__ void fill_kernel(const void* __restrict__ ei,
                            const float* __restrict__ ew) {
    int e = blockIdx.x * blockDim.x + threadIdx.x;
    if (e >= N_EDGES) return;
    int mode64 = g_idx64;
    int s = load_idx(ei, e, 0, mode64);
    int d = load_idx(ei, e, 1, mode64);
    if ((unsigned)s >= N_NODES || (unsigned)d >= N_NODES) return;
    int p = atomicAdd(&g_pos[d], 1);
    g_edge[p] = make_int2(s, __float_as_int(__ldg(&ew[e])));
}

// ---------------- gather1: agg1[n] = mean over in-edges of x[src]*w ----------------
// one warp per node; lane covers 4 consecutive features; 8-way unrolled (MLP=8)
__global__ void gather1_kernel(const float* __restrict__ x) {
    int n = (blockIdx.x * blockDim.x + threadIdx.x) >> 5;
    if (n >= N_NODES) return;
    int lane = threadIdx.x & 31;
    int off = g_off[n], end = g_off[n + 1];
    float4 a0 = make_float4(0.f, 0.f, 0.f, 0.f);
    float4 a1 = a0, a2 = a0, a3 = a0, a4 = a0, a5 = a0, a6 = a0, a7 = a0;
    int i = off;
    for (; i + 8 <= end; i += 8) {
        int2 e0 = __ldg(reinterpret_cast<const int2*>(g_edge) + i + 0);
        int2 e1 = __ldg(reinterpret_cast<const int2*>(g_edge) + i + 1);
        int2 e2 = __ldg(reinterpret_cast<const int2*>(g_edge) + i + 2);
        int2 e3 = __ldg(reinterpret_cast<const int2*>(g_edge) + i + 3);
        int2 e4 = __ldg(reinterpret_cast<const int2*>(g_edge) + i + 4);
        int2 e5 = __ldg(reinterpret_cast<const int2*>(g_edge) + i + 5);
        int2 e6 = __ldg(reinterpret_cast<const int2*>(g_edge) + i + 6);
        int2 e7 = __ldg(reinterpret_cast<const int2*>(g_edge) + i + 7);
        float4 v0 = __ldg(reinterpret_cast<const float4*>(x + (size_t)e0.x * D_IN) + lane);
        float4 v1 = __ldg(reinterpret_cast<const float4*>(x + (size_t)e1.x * D_IN) + lane);
        float4 v2 = __ldg(reinterpret_cast<const float4*>(x + (size_t)e2.x * D_IN) + lane);
        float4 v3 = __ldg(reinterpret_cast<const float4*>(x + (size_t)e3.x * D_IN) + lane);
        float4 v4 = __ldg(reinterpret_cast<const float4*>(x + (size_t)e4.x * D_IN) + lane);
        float4 v5 = __ldg(reinterpret_cast<const float4*>(x + (size_t)e5.x * D_IN) + lane);
        float4 v6 = __ldg(reinterpret_cast<const float4*>(x + (size_t)e6.x * D_IN) + lane);
        float4 v7 = __ldg(reinterpret_cast<const float4*>(x + (size_t)e7.x * D_IN) + lane);
        float w0 = __int_as_float(e0.y), w1 = __int_as_float(e1.y);
        float w2 = __int_as_float(e2.y), w3 = __int_as_float(e3.y);
        float w4 = __int_as_float(e4.y), w5 = __int_as_float(e5.y);
        float w6 = __int_as_float(e6.y), w7 = __int_as_float(e7.y);
        a0.x = fmaf(v0.x, w0, a0.x); a0.y = fmaf(v0.y, w0, a0.y);
        a0.z = fmaf(v0.z, w0, a0.z); a0.w = fmaf(v0.w, w0, a0.w);
        a1.x = fmaf(v1.x, w1, a1.x); a1.y = fmaf(v1.y, w1, a1.y);
        a1.z = fmaf(v1.z, w1, a1.z); a1.w = fmaf(v1.w, w1, a1.w);
        a2.x = fmaf(v2.x, w2, a2.x); a2.y = fmaf(v2.y, w2, a2.y);
        a2.z = fmaf(v2.z, w2, a2.z); a2.w = fmaf(v2.w, w2, a2.w);
        a3.x = fmaf(v3.x, w3, a3.x); a3.y = fmaf(v3.y, w3, a3.y);
        a3.z = fmaf(v3.z, w3, a3.z); a3.w = fmaf(v3.w, w3, a3.w);
        a4.x = fmaf(v4.x, w4, a4.x); a4.y = fmaf(v4.y, w4, a4.y);
        a4.z = fmaf(v4.z, w4, a4.z); a4.w = fmaf(v4.w, w4, a4.w);
        a5.x = fmaf(v5.x, w5, a5.x); a5.y = fmaf(v5.y, w5, a5.y);
        a5.z = fmaf(v5.z, w5, a5.z); a5.w = fmaf(v5.w, w5, a5.w);
        a6.x = fmaf(v6.x, w6, a6.x); a6.y = fmaf(v6.y, w6, a6.y);
        a6.z = fmaf(v6.z, w6, a6.z); a6.w = fmaf(v6.w, w6, a6.w);
        a7.x = fmaf(v7.x, w7, a7.x); a7.y = fmaf(v7.y, w7, a7.y);
        a7.z = fmaf(v7.z, w7, a7.z); a7.w = fmaf(v7.w, w7, a7.w);
    }
    for (; i < end; ++i) {
        int2 e = __ldg(reinterpret_cast<const int2*>(g_edge) + i);
        float w = __int_as_float(e.y);
        float4 v = __ldg(reinterpret_cast<const float4*>(x + (size_t)e.x * D_IN) + lane);
        a0.x = fmaf(v.x, w, a0.x); a0.y = fmaf(v.y, w, a0.y);
        a0.z = fmaf(v.z, w, a0.z); a0.w = fmaf(v.w, w, a0.w);
    }
    a0.x += (a1.x + a2.x) + (a3.x + a4.x) + (a5.x + a6.x) + a7.x;
    a0.y += (a1.y + a2.y) + (a3.y + a4.y) + (a5.y + a6.y) + a7.y;
    a0.z += (a1.z + a2.z) + (a3.z + a4.z) + (a5.z + a6.z) + a7.z;
    a0.w += (a1.w + a2.w) + (a3.w + a4.w) + (a5.w + a6.w) + a7.w;
    float inv = 1.0f / fmaxf((float)(end - off), 1.0f);
    a0.x *= inv; a0.y *= inv; a0.z *= inv; a0.w *= inv;
    reinterpret_cast<float4*>(g_agg1 + (size_t)n * D_IN)[lane] = a0;
}

// ---------------- layer 1 (f32x2, K-packed, 2ch x 8node blocking) -------------------
// h = relu(agg1@Wl1^T + b1 + x@Wr1^T). 512 threads, 64-node tile.
// j = t&63 -> channels j and j+64 ; grp = t>>6 -> 8 nodes.
// Feature LDS shared across both channels -> FMA-bound (80 crossbar vs 128 fma cyc/chunk).
#define L1_WPAD 132
#define L1_TILE 64
#define L1_SMEM_BYTES (2 * 128 * L1_WPAD * 4 + 2 * L1_TILE * 128 * 4)  // 200704
__global__ void layer1_kernel(const float* __restrict__ x,
                              const float* __restrict__ Wl,
                              const float* __restrict__ bl,
                              const float* __restrict__ Wr,
                              float* __restrict__ hout) {
    extern __shared__ float sm[];
    float* wl = sm;                             // [128][132] native [j][k]
    float* wr = sm + 128 * L1_WPAD;
    float* fa = sm + 2 * 128 * L1_WPAD;         // [64][128]
    float* fx = fa + L1_TILE * 128;
    int t = threadIdx.x;
    for (int i = t; i < 128 * 128; i += 512) {
        int j = i >> 7, k = i & 127;
        wl[j * L1_WPAD + k] = Wl[i];
        wr[j * L1_WPAD + k] = Wr[i];
    }
    int j = t & 63;                             // channels j, j+64
    int grp = t >> 6;                           // 0..7 -> nodes grp*8 .. grp*8+7
    float bj0 = bl[j], bj1 = bl[j + 64];
    __syncthreads();
    const int NT = (N_NODES + L1_TILE - 1) / L1_TILE;   // 1563 (last tile partial)
    for (int tile = blockIdx.x; tile < NT; tile += gridDim.x) {
        int base = tile * L1_TILE;
        __syncthreads();
        for (int i = t; i < L1_TILE * 128; i += 512) {
            int n = i >> 7, k = i & 127;
            int node = base + n; if (node >= N_NODES) node = N_NODES - 1;
            fa[i] = g_agg1[(size_t)node * 128 + k];
            fx[i] = x[(size_t)node * 128 + k];
        }
        __syncthreads();
        unsigned long long acc0[8], acc1[8];
        #pragma unroll
        for (int n = 0; n < 8; ++n) { acc0[n] = 0ull; acc1[n] = 0ull; }
        const float* fan = fa + grp * 8 * 128;
        const float* fxn = fx + grp * 8 * 128;
        const float* wl0 = wl + j * L1_WPAD;
        const float* wl1 = wl + (j + 64) * L1_WPAD;
        const float* wr0 = wr + j * L1_WPAD;
        const float* wr1 = wr + (j + 64) * L1_WPAD;
        #pragma unroll 4
        for (int k = 0; k < 128; k += 4) {
            ulonglong2 wla = *reinterpret_cast<const ulonglong2*>(wl0 + k);
            ulonglong2 wlb = *reinterpret_cast<const ulonglong2*>(wl1 + k);
            ulonglong2 wra = *reinterpret_cast<const ulonglong2*>(wr0 + k);
            ulonglong2 wrb = *reinterpret_cast<const ulonglong2*>(wr1 + k);
            #pragma unroll
            for (int n = 0; n < 8; ++n) {
                ulonglong2 f_a = *reinterpret_cast<const ulonglong2*>(fan + n * 128 + k);
                ulonglong2 f_x = *reinterpret_cast<const ulonglong2*>(fxn + n * 128 + k);
                acc0[n] = ffma2(wla.x, f_a.x, acc0[n]);
                acc0[n] = ffma2(wla.y, f_a.y, acc0[n]);
                acc0[n] = ffma2(wra.x, f_x.x, acc0[n]);
                acc0[n] = ffma2(wra.y, f_x.y, acc0[n]);
                acc1[n] = ffma2(wlb.x, f_a.x, acc1[n]);
                acc1[n] = ffma2(wlb.y, f_a.y, acc1[n]);
                acc1[n] = ffma2(wrb.x, f_x.x, acc1[n]);
                acc1[n] = ffma2(wrb.y, f_x.y, acc1[n]);
            }
        }
        #pragma unroll
        for (int n = 0; n < 8; ++n) {
            int node = base + grp * 8 + n;
            if (node < N_NODES) {
                float lo, hi;
                unpack2(acc0[n], lo, hi);
                hout[(size_t)node * 128 + j] = fmaxf(lo + hi + bj0, 0.f);
                unpack2(acc1[n], lo, hi);
                hout[(size_t)node * 128 + j + 64] = fmaxf(lo + hi + bj1, 0.f);
            }
        }
    }
}

// ---------------- tmat2 (f32x2, K-packed, fused): t = h@Wl2^T ; r = h@Wr2^T + b2 --------
#define T2_WPAD 132
#define T2_TILE 32
#define T2_SMEM_BYTES (2 * 64 * T2_WPAD * 4 + T2_TILE * 128 * 4)  // 83968
__global__ void tmat2_kernel(const float* __restrict__ h,
                             const float* __restrict__ Wl2,
                             const float* __restrict__ Wr2,
                             const float* __restrict__ b2) {
    extern __shared__ float sm[];
    float* wl = sm;                             // [64][132] native [j][k]
    float* wr = sm + 64 * T2_WPAD;
    float* fh = sm + 2 * 64 * T2_WPAD;          // [32][128]
    int t = threadIdx.x;
    for (int i = t; i < 64 * 128; i += 512) {
        int j = i >> 7, k = i & 127;
        wl[j * T2_WPAD + k] = Wl2[i];
        wr[j * T2_WPAD + k] = Wr2[i];
    }
    int j = t & 63;
    int grp = t >> 6;                           // 0..7 -> nodes grp*4 .. grp*4+3
    float bj = b2[j];
    __syncthreads();
    const int NT = N_NODES / T2_TILE;           // 3125
    for (int tile = blockIdx.x; tile < NT; tile += gridDim.x) {
        int base = tile * T2_TILE;
        __syncthreads();
        for (int i = t; i < T2_TILE * 128; i += 512)
            fh[i] = h[(size_t)base * 128 + i];
        __syncthreads();
        unsigned long long tac[4], rac[4];
        #pragma unroll
        for (int n = 0; n < 4; ++n) { tac[n] = 0ull; rac[n] = 0ull; }
        const float* fn = fh + grp * 4 * 128;
        const float* wlj = wl + j * T2_WPAD;
        const float* wrj = wr + j * T2_WPAD;
        #pragma unroll 4
        for (int k = 0; k < 128; k += 4) {
            ulonglong2 w_l = *reinterpret_cast<const ulonglong2*>(wlj + k);
            ulonglong2 w_r = *reinterpret_cast<const ulonglong2*>(wrj + k);
            #pragma unroll
            for (int n = 0; n < 4; ++n) {
                ulonglong2 f = *reinterpret_cast<const ulonglong2*>(fn + n * 128 + k);
                tac[n] = ffma2(w_l.x, f.x, tac[n]);
                tac[n] = ffma2(w_l.y, f.y, tac[n]);
                rac[n] = ffma2(w_r.x, f.x, rac[n]);
                rac[n] = ffma2(w_r.y, f.y, rac[n]);
            }
        }
        #pragma unroll
        for (int n = 0; n < 4; ++n) {
            int node = base + grp * 4 + n;
            float lo, hi;
            unpack2(tac[n], lo, hi);
            g_t[(size_t)node * 64 + j] = lo + hi;
            unpack2(rac[n], lo, hi);
            g_r[(size_t)node * 64 + j] = lo + hi + bj;
        }
    }
}

// ---------------- gather2 + epilogue: out = mean-agg(t) + r ----------------
// HALF-warp per node (16 lanes x float4 = 64 ch); 4-way unrolled
__global__ void gather2_kernel(float* __restrict__ out) {
    int gt = blockIdx.x * blockDim.x + threadIdx.x;
    int n = gt >> 4;
    if (n >= N_NODES) return;
    int sub = gt & 15;
    int off = g_off[n], end = g_off[n + 1];
    float4 a0 = make_float4(0.f, 0.f, 0.f, 0.f);
    float4 a1 = a0, a2 = a0, a3 = a0;
    int i = off;
    for (; i + 4 <= end; i += 4) {
        int2 e0 = __ldg(reinterpret_cast<const int2*>(g_edge) + i + 0);
        int2 e1 = __ldg(reinterpret_cast<const int2*>(g_edge) + i + 1);
        int2 e2 = __ldg(reinterpret_cast<const int2*>(g_edge) + i + 2);
        int2 e3 = __ldg(reinterpret_cast<const int2*>(g_edge) + i + 3);
        float4 v0 = __ldg(reinterpret_cast<const float4*>(g_t + (size_t)e0.x * D_OUT) + sub);
        float4 v1 = __ldg(reinterpret_cast<const float4*>(g_t + (size_t)e1.x * D_OUT) + sub);
        float4 v2 = __ldg(reinterpret_cast<const float4*>(g_t + (size_t)e2.x * D_OUT) + sub);
        float4 v3 = __ldg(reinterpret_cast<const float4*>(g_t + (size_t)e3.x * D_OUT) + sub);
        float w0 = __int_as_float(e0.y), w1 = __int_as_float(e1.y);
        float w2 = __int_as_float(e2.y), w3 = __int_as_float(e3.y);
        a0.x = fmaf(v0.x, w0, a0.x); a0.y = fmaf(v0.y, w0, a0.y);
        a0.z = fmaf(v0.z, w0, a0.z); a0.w = fmaf(v0.w, w0, a0.w);
        a1.x = fmaf(v1.x, w1, a1.x); a1.y = fmaf(v1.y, w1, a1.y);
        a1.z = fmaf(v1.z, w1, a1.z); a1.w = fmaf(v1.w, w1, a1.w);
        a2.x = fmaf(v2.x, w2, a2.x); a2.y = fmaf(v2.y, w2, a2.y);
        a2.z = fmaf(v2.z, w2, a2.z); a2.w = fmaf(v2.w, w2, a2.w);
        a3.x = fmaf(v3.x, w3, a3.x); a3.y = fmaf(v3.y, w3, a3.y);
        a3.z = fmaf(v3.z, w3, a3.z); a3.w = fmaf(v3.w, w3, a3.w);
    }
    for (; i < end; ++i) {
        int2 e = __ldg(reinterpret_cast<const int2*>(g_edge) + i);
        float w = __int_as_float(e.y);
        float4 v = __ldg(reinterpret_cast<const float4*>(g_t + (size_t)e.x * D_OUT) + sub);
        a0.x = fmaf(v.x, w, a0.x); a0.y = fmaf(v.y, w, a0.y);
        a0.z = fmaf(v.z, w, a0.z); a0.w = fmaf(v.w, w, a0.w);
    }
    a0.x += (a1.x + a2.x) + a3.x;
    a0.y += (a1.y + a2.y) + a3.y;
    a0.z += (a1.z + a2.z) + a3.z;
    a0.w += (a1.w + a2.w) + a3.w;
    float inv = 1.0f / fmaxf((float)(end - off), 1.0f);
    float4 rv = __ldg(reinterpret_cast<const float4*>(g_r + (size_t)n * D_OUT) + sub);
    a0.x = fmaf(a0.x, inv, rv.x);
    a0.y = fmaf(a0.y, inv, rv.y);
    a0.z = fmaf(a0.z, inv, rv.z);
    a0.w = fmaf(a0.w, inv, rv.w);
    reinterpret_cast<float4*>(out + (size_t)n * D_OUT)[sub] = a0;
}

// ---------------- launch ----------------
extern "C" void kernel_launch(void* const* d_in, const int* in_sizes, int n_in,
                              void* d_out, int out_size) {
    (void)in_sizes; (void)n_in;
    const float* x   = (const float*)d_in[0];
    const void*  ei  = d_in[1];                 // int32 or int64, detected on device
    const float* ew  = (const float*)d_in[2];
    const float* Wl1 = (const float*)d_in[3];
    const float* bl1 = (const float*)d_in[4];
    const float* Wr1 = (const float*)d_in[5];
    const float* Wl2 = (const float*)d_in[6];
    const float* bl2 = (const float*)d_in[7];
    const float* Wr2 = (const float*)d_in[8];

    float* hptr;
    float* lptr;
    const size_t full = (size_t)N_NODES * (D_HID + D_OUT);
    if ((size_t)out_size >= full) {
        hptr = (float*)d_out;
        lptr = hptr + (size_t)N_NODES * D_HID;
    } else {
        void* sym = nullptr;
        cudaGetSymbolAddress(&sym, g_h);
        hptr = (float*)sym;
        lptr = (float*)d_out;
    }

    cudaFuncSetAttribute(layer1_kernel,
                         cudaFuncAttributeMaxDynamicSharedMemorySize, L1_SMEM_BYTES);
    cudaFuncSetAttribute(tmat2_kernel,
                         cudaFuncAttributeMaxDynamicSharedMemorySize, T2_SMEM_BYTES);

    detect_kernel<<<1, 256>>>((const int*)ei);
    zero_deg_kernel<<<NBLK, 256>>>();
    hist_kernel<<<N_EDGES / 256, 256>>>(ei);
    blocksum_kernel<<<NBLK, 256>>>();
    scan_bsum_kernel<<<1, 512>>>();
    offsets_kernel<<<NBLK, 256>>>();
    fill_kernel<<<N_EDGES / 256, 256>>>(ei, ew);
    gather1_kernel<<<(N_NODES * 32 + 255) / 256, 256>>>(x);
    layer1_kernel<<<148, 512, L1_SMEM_BYTES>>>(x, Wl1, bl1, Wr1, hptr);
    tmat2_kernel<<<296, 512, T2_SMEM_BYTES>>>(hptr, Wl2, Wr2, bl2);
    gather2_kernel<<<(N_NODES * 16 + 255) / 256, 256>>>(lptr);
}